// round 5
// baseline (speedup 1.0000x reference)
#include <cuda_runtime.h>
#include <cuda_bf16.h>
#include <math.h>
#include <stdint.h>

// Problem constants
#define T_STEPS 1000
#define BATCH   128
#define N_IN    3
#define N_H     256
#define N_PC    256
#define N_HD    12
#define N_IC    268
#define M_ROWS  (T_STEPS * BATCH)   // 128000

// Output layout (float32, concatenated in reference tuple order)
#define OFF_HD   0L
#define OFF_PC   (OFF_HD  + (long)T_STEPS * BATCH * N_HD)
#define OFF_BOT  (OFF_PC  + (long)T_STEPS * BATCH * N_PC)
#define OFF_RNN  (OFF_BOT + (long)T_STEPS * BATCH * N_H)
#define OFF_CELL (OFF_RNN + (long)T_STEPS * BATCH * N_H)

// Tile swizzle: rows of 512B; XOR byte-offset bits[4:6] with (row&7).
#define TSWZ(kb, r) ((kb) ^ (((r) & 7) << 4))

// ---------------------------------------------------------------------------
// Device-global scratch (allocation-free)
// ---------------------------------------------------------------------------
__device__ float g_h0[BATCH * N_H];
__device__ float g_c0[BATCH * N_H];
// Y bf16, pre-swizzled tile images: tile t = [128 batch rows][256 h], 64KB each.
__device__ __nv_bfloat16 g_yimg[(long)T_STEPS * 128 * 256];
// pc W hi/lo bf16 images per N-half: [hi 64KB | lo 64KB] contiguous.
__device__ __nv_bfloat16 g_wimg[2][65536];
// hd W hi/lo bf16 image: 16 rows (12 used) x 256 k: [hi 8KB | lo 8KB].
__device__ __nv_bfloat16 g_hdimg[8192];

// ---------------------------------------------------------------------------
// PTX helpers (base-arch only)
// ---------------------------------------------------------------------------
__device__ __forceinline__ uint32_t smem_u32(const void* p) {
    uint32_t a;
    asm("{ .reg .u64 t; cvta.to.shared.u64 t, %1; cvt.u32.u64 %0, t; }" : "=r"(a) : "l"(p));
    return a;
}
__device__ __forceinline__ void cp_async16(uint32_t dst, const void* src) {
    asm volatile("cp.async.cg.shared.global [%0], [%1], 16;" :: "r"(dst), "l"(src) : "memory");
}
__device__ __forceinline__ void cp_async_wait_all() {
    asm volatile("cp.async.commit_group;\ncp.async.wait_group 0;" ::: "memory");
}
__device__ __forceinline__ void ldsm4(uint32_t& r0, uint32_t& r1, uint32_t& r2, uint32_t& r3,
                                      uint32_t addr) {
    asm volatile("ldmatrix.sync.aligned.m8n8.x4.shared.b16 {%0,%1,%2,%3}, [%4];"
                 : "=r"(r0), "=r"(r1), "=r"(r2), "=r"(r3) : "r"(addr));
}
__device__ __forceinline__ void mma16816(float* c, const uint32_t* a, uint32_t b0, uint32_t b1) {
    asm volatile("mma.sync.aligned.m16n8k16.row.col.f32.bf16.bf16.f32 "
                 "{%0,%1,%2,%3}, {%4,%5,%6,%7}, {%8,%9}, {%0,%1,%2,%3};"
                 : "+f"(c[0]), "+f"(c[1]), "+f"(c[2]), "+f"(c[3])
                 : "r"(a[0]), "r"(a[1]), "r"(a[2]), "r"(a[3]), "r"(b0), "r"(b1));
}
__device__ __forceinline__ void stcs4(float* p, float4 v) {
    asm volatile("st.global.cs.v4.f32 [%0], {%1,%2,%3,%4};"
                 :: "l"(p), "f"(v.x), "f"(v.y), "f"(v.z), "f"(v.w) : "memory");
}
__device__ __forceinline__ void stcs1(float* p, float v) {
    asm volatile("st.global.cs.f32 [%0], %1;" :: "l"(p), "f"(v) : "memory");
}
__device__ __forceinline__ void stcs2(float* p, float2 v) {
    asm volatile("st.global.cs.v2.f32 [%0], {%1,%2};" :: "l"(p), "f"(v.x), "f"(v.y) : "memory");
}

// ---------------------------------------------------------------------------
// Kernel 1: initial conditions
// ---------------------------------------------------------------------------
__global__ void init_kernel(const float* __restrict__ ic,
                            const float* __restrict__ sew, const float* __restrict__ seb,
                            const float* __restrict__ cew, const float* __restrict__ ceb) {
    __shared__ float icr[N_IC];
    int b = blockIdx.x;
    int h = threadIdx.x;
    for (int i = h; i < N_IC; i += N_H) icr[i] = ic[b * N_IC + i];
    __syncthreads();

    float accS = seb[h];
    float accC = ceb[h];
    #pragma unroll 4
    for (int k = 0; k < N_IC; k++) {
        float v = icr[k];
        accS = fmaf(v, sew[k * N_H + h], accS);
        accC = fmaf(v, cew[k * N_H + h], accC);
    }
    g_h0[b * N_H + h] = 1.0f / (1.0f + expf(-accS));
    g_c0[b * N_H + h] = 1.0f / (1.0f + expf(-accC));
}

// ---------------------------------------------------------------------------
// Kernel 2a: pc W -> (hi, lo) bf16, pre-swizzled images per N-half.
// ---------------------------------------------------------------------------
__global__ void wconv_kernel(const float* __restrict__ W) {
    int k = blockIdx.x;    // 0..255
    int n = threadIdx.x;   // 0..255
    float w = W[k * 256 + n];
    __nv_bfloat16 hi = __float2bfloat16(w);
    __nv_bfloat16 lo = __float2bfloat16(w - __bfloat162float(hi));
    int nh = n >> 7, nl = n & 127;
    int byteoff = nl * 512 + TSWZ(k * 2, nl);
    g_wimg[nh][byteoff >> 1]           = hi;
    g_wimg[nh][32768 + (byteoff >> 1)] = lo;
}

// Kernel 2b: hd W [256,12] -> padded 16-row hi/lo image.
__global__ void wconv_hd_kernel(const float* __restrict__ W) {
    int n = blockIdx.x;    // 0..15
    int k = threadIdx.x;   // 0..255
    float w = (n < N_HD) ? W[k * N_HD + n] : 0.0f;
    __nv_bfloat16 hi = __float2bfloat16(w);
    __nv_bfloat16 lo = __float2bfloat16(w - __bfloat162float(hi));
    int byteoff = n * 512 + TSWZ(k * 2, n);
    g_hdimg[byteoff >> 1]          = hi;
    g_hdimg[4096 + (byteoff >> 1)] = lo;
}

// ---------------------------------------------------------------------------
// Kernel 3: recurrence. grid=(128,2) (batch, h-half), 128 threads (one per h).
// Stores ONLY: s (fp32, streaming) + y (bf16 pre-swizzled image).
// ---------------------------------------------------------------------------
__global__ void __launch_bounds__(128) rec_kernel(const float* __restrict__ x,
                                                  const float* __restrict__ iw,
                                                  const float* __restrict__ lvec,
                                                  const float* __restrict__ bvec,
                                                  float* __restrict__ out) {
    __shared__ float xs[T_STEPS * N_IN];  // 12 KB
    const int b = blockIdx.x;
    const int h = blockIdx.y * 128 + threadIdx.x;

    for (int i = threadIdx.x; i < T_STEPS * N_IN; i += 128) {
        int t = i / N_IN, c = i - t * N_IN;
        xs[i] = x[((long)t * BATCH + b) * N_IN + c];
    }

    const float w0 = iw[0 * N_H + h];
    const float w1 = iw[1 * N_H + h];
    const float w2 = iw[2 * N_H + h];
    const float lv = lvec[h];
    const float bv = bvec[h];
    float y = g_h0[b * N_H + h];
    float s = g_c0[b * N_H + h];
    __syncthreads();

    float* sp = out + OFF_CELL + (long)b * N_H + h;
    __nv_bfloat16* yi = g_yimg + ((b * 512 + TSWZ(h * 2, b)) >> 1);

    const long strideT = (long)BATCH * N_H;  // 32768

    for (int t = 0; t < T_STEPS; t++) {
        const float x0 = xs[t * 3 + 0];
        const float x1 = xs[t * 3 + 1];
        const float x2 = xs[t * 3 + 2];
        float xw  = fmaf(x2, w2, fmaf(x1, w1, x0 * w0));
        float pre = xw + y + lv * s * (1.0f - y);
        s = fmaxf(pre, 0.0f);
        y = (s + bv > 0.0f) ? 1.0f : 0.0f;

        stcs1(sp + (long)t * strideT, s);
        yi[(long)t * 32768] = __float2bfloat16(y);
    }
}

// ---------------------------------------------------------------------------
// Kernel 4: pc GEMM via HMMA + fused hd + fused fp32-y reconstruction.
// grid=(1000,2), 256 thr, 208KB SMEM.
// nh==0 blocks: also compute hd[128,12] (warp_n==0 warps) and dump the A tile
// as fp32 into BOT and RNN regions (stores drain under the MMA mainloop).
// ---------------------------------------------------------------------------
#define SM_A   0
#define SM_BH  65536
#define SM_HD  196608
#define SM_TOT 212992

__global__ void __launch_bounds__(256) pc_gemm(const float* __restrict__ pcb,
                                               const float* __restrict__ hdb,
                                               float* __restrict__ out) {
    extern __shared__ char smem[];
    uint32_t sb = smem_u32(smem);
    const int tid = threadIdx.x, wid = tid >> 5, lane = tid & 31;
    const int m = blockIdx.x, nh = blockIdx.y;
    const int warp_m = wid & 3, warp_n = wid >> 2;
    const bool do_hd = (nh == 0) && (warp_n == 0);

    // Linear bulk copies of pre-swizzled images
    {
        const char* gA = (const char*)(g_yimg + (long)m * 32768);
        const char* gW = (const char*)(g_wimg[nh]);
        #pragma unroll
        for (int i = 0; i < 16; i++)
            cp_async16(sb + SM_A + (tid + i * 256) * 16, gA + (tid + i * 256) * 16);
        #pragma unroll
        for (int i = 0; i < 32; i++)
            cp_async16(sb + SM_BH + (tid + i * 256) * 16, gW + (tid + i * 256) * 16);
        if (nh == 0) {
            const char* gH = (const char*)g_hdimg;
            #pragma unroll
            for (int i = 0; i < 4; i++)
                cp_async16(sb + SM_HD + (tid + i * 256) * 16, gH + (tid + i * 256) * 16);
        }
        cp_async_wait_all();
    }
    __syncthreads();

    // fp32 y reconstruction: nh==0 blocks dump the A tile to BOT and RNN.
    // Thread -> (row r = tid>>1, col-half ch = (tid&1)*128): 128 elems each.
    if (nh == 0) {
        const int r  = tid >> 1;
        const int c0 = (tid & 1) * 128;
        const long grow = (long)m * BATCH + r;
        float* bot = out + OFF_BOT + grow * N_H;
        float* rnn = out + OFF_RNN + grow * N_H;
        #pragma unroll
        for (int i = 0; i < 16; i++) {
            int c = c0 + i * 8;
            uint4 v = *(uint4*)(smem + SM_A + r * 512 + TSWZ(c * 2, r));
            float2 f0 = __bfloat1622float2(*(__nv_bfloat162*)&v.x);
            float2 f1 = __bfloat1622float2(*(__nv_bfloat162*)&v.y);
            float2 f2 = __bfloat1622float2(*(__nv_bfloat162*)&v.z);
            float2 f3 = __bfloat1622float2(*(__nv_bfloat162*)&v.w);
            float4 lo4 = make_float4(f0.x, f0.y, f1.x, f1.y);
            float4 hi4 = make_float4(f2.x, f2.y, f3.x, f3.y);
            stcs4(bot + c, lo4);
            stcs4(bot + c + 4, hi4);
            stcs4(rnn + c, lo4);
            stcs4(rnn + c + 4, hi4);
        }
    }

    float acc[2][8][4];
    #pragma unroll
    for (int i = 0; i < 2; i++)
        #pragma unroll
        for (int j = 0; j < 8; j++)
            #pragma unroll
            for (int q = 0; q < 4; q++) acc[i][j][q] = 0.0f;
    float acch[2][2][4];
    #pragma unroll
    for (int i = 0; i < 2; i++)
        #pragma unroll
        for (int j = 0; j < 2; j++)
            #pragma unroll
            for (int q = 0; q < 4; q++) acch[i][j][q] = 0.0f;

    const int arow0 = warp_m * 32 + (lane & 15);
    const int brow0 = warp_n * 64 + (lane & 15);
    const int hrow0 = (lane & 15);
    const int ksub  = (lane >> 4) * 16;

    #pragma unroll
    for (int pass = 0; pass < 2; pass++) {
        const uint32_t bbase = sb + SM_BH + pass * 65536;
        const uint32_t hbase = sb + SM_HD + pass * 8192;
        #pragma unroll
        for (int k16 = 0; k16 < 16; k16++) {
            const int kb = k16 * 32 + ksub;
            uint32_t a[2][4], bfr[4][4];
            #pragma unroll
            for (int mi = 0; mi < 2; mi++) {
                int r = arow0 + mi * 16;
                ldsm4(a[mi][0], a[mi][1], a[mi][2], a[mi][3],
                      sb + SM_A + r * 512 + TSWZ(kb, r));
            }
            #pragma unroll
            for (int ni = 0; ni < 4; ni++) {
                int r = brow0 + ni * 16;
                ldsm4(bfr[ni][0], bfr[ni][1], bfr[ni][2], bfr[ni][3],
                      bbase + r * 512 + TSWZ(kb, r));
            }
            #pragma unroll
            for (int mi = 0; mi < 2; mi++)
                #pragma unroll
                for (int ni = 0; ni < 4; ni++) {
                    mma16816(acc[mi][ni * 2],     a[mi], bfr[ni][0], bfr[ni][2]);
                    mma16816(acc[mi][ni * 2 + 1], a[mi], bfr[ni][1], bfr[ni][3]);
                }
            if (do_hd) {
                uint32_t hb[4];
                ldsm4(hb[0], hb[1], hb[2], hb[3],
                      hbase + hrow0 * 512 + TSWZ(kb, hrow0));
                #pragma unroll
                for (int mi = 0; mi < 2; mi++) {
                    mma16816(acch[mi][0], a[mi], hb[0], hb[2]);
                    mma16816(acch[mi][1], a[mi], hb[1], hb[3]);
                }
            }
        }
    }

    // Epilogue: pc. c0,c1: row g; c2,c3: row g+8.
    const int g  = lane >> 2;
    const int c2 = (lane & 3) * 2;
    const long rowBase = (long)m * 128 + warp_m * 32;
    const int  colBase = nh * 128 + warp_n * 64;

    float2 bias2[8];
    #pragma unroll
    for (int ni = 0; ni < 8; ni++) {
        bias2[ni].x = __ldg(pcb + colBase + ni * 8 + c2);
        bias2[ni].y = __ldg(pcb + colBase + ni * 8 + c2 + 1);
    }

    float* outpc = out + OFF_PC;
    #pragma unroll
    for (int mi = 0; mi < 2; mi++) {
        float* r0 = outpc + (rowBase + mi * 16 + g) * N_PC + colBase + c2;
        float* r1 = r0 + 8 * N_PC;
        #pragma unroll
        for (int ni = 0; ni < 8; ni++) {
            stcs2(r0 + ni * 8, make_float2(acc[mi][ni][0] + bias2[ni].x,
                                           acc[mi][ni][1] + bias2[ni].y));
            stcs2(r1 + ni * 8, make_float2(acc[mi][ni][2] + bias2[ni].x,
                                           acc[mi][ni][3] + bias2[ni].y));
        }
    }

    // Epilogue: hd (cols 0..11 of the padded 16)
    if (do_hd) {
        float* outhd = out + OFF_HD;
        float hb0x = __ldg(hdb + c2);
        float hb0y = __ldg(hdb + c2 + 1);
        float hb1x = 0.0f, hb1y = 0.0f;
        if (c2 < 4) {
            hb1x = __ldg(hdb + 8 + c2);
            hb1y = __ldg(hdb + 8 + c2 + 1);
        }
        #pragma unroll
        for (int mi = 0; mi < 2; mi++) {
            long r = rowBase + mi * 16 + g;
            float* o0 = outhd + r * N_HD;
            float* o1 = o0 + 8L * N_HD;
            stcs2(o0 + c2, make_float2(acch[mi][0][0] + hb0x, acch[mi][0][1] + hb0y));
            stcs2(o1 + c2, make_float2(acch[mi][0][2] + hb0x, acch[mi][0][3] + hb0y));
            if (c2 < 4) {
                stcs2(o0 + 8 + c2, make_float2(acch[mi][1][0] + hb1x, acch[mi][1][1] + hb1y));
                stcs2(o1 + 8 + c2, make_float2(acch[mi][1][2] + hb1x, acch[mi][1][3] + hb1y));
            }
        }
    }
}

// ---------------------------------------------------------------------------
extern "C" void kernel_launch(void* const* d_in, const int* in_sizes, int n_in,
                              void* d_out, int out_size) {
    const float* x    = (const float*)d_in[0];
    const float* ic   = (const float*)d_in[1];
    const float* iw   = (const float*)d_in[2];
    const float* l    = (const float*)d_in[3];
    const float* b    = (const float*)d_in[4];
    const float* sew  = (const float*)d_in[5];
    const float* seb  = (const float*)d_in[6];
    const float* cew  = (const float*)d_in[7];
    const float* ceb  = (const float*)d_in[8];
    const float* pcw  = (const float*)d_in[9];
    const float* pcb  = (const float*)d_in[10];
    const float* hdw  = (const float*)d_in[11];
    const float* hdb  = (const float*)d_in[12];
    float* out = (float*)d_out;

    cudaFuncSetAttribute(pc_gemm, cudaFuncAttributeMaxDynamicSharedMemorySize, SM_TOT);

    init_kernel<<<BATCH, N_H>>>(ic, sew, seb, cew, ceb);
    wconv_kernel<<<256, 256>>>(pcw);
    wconv_hd_kernel<<<16, 256>>>(hdw);
    rec_kernel<<<dim3(BATCH, 2), 128>>>(x, iw, l, b, out);
    pc_gemm<<<dim3(T_STEPS, 2), 256, SM_TOT>>>(pcb, hdb, out);
}

// round 6
// speedup vs baseline: 1.4232x; 1.4232x over previous
#include <cuda_runtime.h>
#include <cuda_fp16.h>
#include <math.h>
#include <stdint.h>

// Problem constants
#define T_STEPS 1000
#define BATCH   128
#define N_IN    3
#define N_H     256
#define N_PC    256
#define N_HD    12
#define N_IC    268
#define M_ROWS  (T_STEPS * BATCH)   // 128000

// Output layout (float32, concatenated in reference tuple order)
#define OFF_HD   0L
#define OFF_PC   (OFF_HD  + (long)T_STEPS * BATCH * N_HD)
#define OFF_BOT  (OFF_PC  + (long)T_STEPS * BATCH * N_PC)
#define OFF_RNN  (OFF_BOT + (long)T_STEPS * BATCH * N_H)
#define OFF_CELL (OFF_RNN + (long)T_STEPS * BATCH * N_H)

// Tile swizzle: rows of 512B; XOR byte-offset bits[4:6] with (row&7).
#define TSWZ(kb, r) ((kb) ^ (((r) & 7) << 4))

// ---------------------------------------------------------------------------
// Device-global scratch (allocation-free)
// ---------------------------------------------------------------------------
__device__ float g_h0[BATCH * N_H];
__device__ float g_c0[BATCH * N_H];
// Y fp16, pre-swizzled tile images: tile t = [128 batch rows][256 h], 64KB each.
__device__ __half g_yimg[(long)T_STEPS * 128 * 256];
// pc W fp16 images per N-half: 128 rows x 256 k = 64KB each.
__device__ __half g_wimg[2][32768];
// hd W fp16 image: 16 rows (12 used) x 256 k = 8KB.
__device__ __half g_hdimg[4096];

// ---------------------------------------------------------------------------
// PTX helpers (base-arch only)
// ---------------------------------------------------------------------------
__device__ __forceinline__ uint32_t smem_u32(const void* p) {
    uint32_t a;
    asm("{ .reg .u64 t; cvta.to.shared.u64 t, %1; cvt.u32.u64 %0, t; }" : "=r"(a) : "l"(p));
    return a;
}
__device__ __forceinline__ void cp_async16(uint32_t dst, const void* src) {
    asm volatile("cp.async.cg.shared.global [%0], [%1], 16;" :: "r"(dst), "l"(src) : "memory");
}
__device__ __forceinline__ void cp_async_wait_all() {
    asm volatile("cp.async.commit_group;\ncp.async.wait_group 0;" ::: "memory");
}
__device__ __forceinline__ void ldsm4(uint32_t& r0, uint32_t& r1, uint32_t& r2, uint32_t& r3,
                                      uint32_t addr) {
    asm volatile("ldmatrix.sync.aligned.m8n8.x4.shared.b16 {%0,%1,%2,%3}, [%4];"
                 : "=r"(r0), "=r"(r1), "=r"(r2), "=r"(r3) : "r"(addr));
}
__device__ __forceinline__ void mma16816(float* c, const uint32_t* a, uint32_t b0, uint32_t b1) {
    asm volatile("mma.sync.aligned.m16n8k16.row.col.f32.f16.f16.f32 "
                 "{%0,%1,%2,%3}, {%4,%5,%6,%7}, {%8,%9}, {%0,%1,%2,%3};"
                 : "+f"(c[0]), "+f"(c[1]), "+f"(c[2]), "+f"(c[3])
                 : "r"(a[0]), "r"(a[1]), "r"(a[2]), "r"(a[3]), "r"(b0), "r"(b1));
}
__device__ __forceinline__ void stcs1(float* p, float v) {
    asm volatile("st.global.cs.f32 [%0], %1;" :: "l"(p), "f"(v) : "memory");
}
__device__ __forceinline__ void stcs2(float* p, float2 v) {
    asm volatile("st.global.cs.v2.f32 [%0], {%1,%2};" :: "l"(p), "f"(v.x), "f"(v.y) : "memory");
}

// ---------------------------------------------------------------------------
// Kernel 1: initial conditions
// ---------------------------------------------------------------------------
__global__ void init_kernel(const float* __restrict__ ic,
                            const float* __restrict__ sew, const float* __restrict__ seb,
                            const float* __restrict__ cew, const float* __restrict__ ceb) {
    __shared__ float icr[N_IC];
    int b = blockIdx.x;
    int h = threadIdx.x;
    for (int i = h; i < N_IC; i += N_H) icr[i] = ic[b * N_IC + i];
    __syncthreads();

    float accS = seb[h];
    float accC = ceb[h];
    #pragma unroll 4
    for (int k = 0; k < N_IC; k++) {
        float v = icr[k];
        accS = fmaf(v, sew[k * N_H + h], accS);
        accC = fmaf(v, cew[k * N_H + h], accC);
    }
    g_h0[b * N_H + h] = 1.0f / (1.0f + expf(-accS));
    g_c0[b * N_H + h] = 1.0f / (1.0f + expf(-accC));
}

// ---------------------------------------------------------------------------
// Kernel 2a: pc W -> fp16, pre-swizzled images per N-half.
// W stored [k=256][n=256]; image row = n (within half), cols = k.
// ---------------------------------------------------------------------------
__global__ void wconv_kernel(const float* __restrict__ W) {
    int k = blockIdx.x;    // 0..255
    int n = threadIdx.x;   // 0..255
    float w = W[k * 256 + n];
    int nh = n >> 7, nl = n & 127;
    int byteoff = nl * 512 + TSWZ(k * 2, nl);
    g_wimg[nh][byteoff >> 1] = __float2half_rn(w);
}

// Kernel 2b: hd W [256,12] -> padded 16-row fp16 image.
__global__ void wconv_hd_kernel(const float* __restrict__ W) {
    int n = blockIdx.x;    // 0..15
    int k = threadIdx.x;   // 0..255
    float w = (n < N_HD) ? W[k * N_HD + n] : 0.0f;
    int byteoff = n * 512 + TSWZ(k * 2, n);
    g_hdimg[byteoff >> 1] = __float2half_rn(w);
}

// ---------------------------------------------------------------------------
// Kernel 3: recurrence. grid=(128,2) (batch, h-half), 128 threads (one per h).
// Stores: y fp32 -> BOT,RNN (streaming); s fp32 -> CELL; y fp16 -> image.
// ---------------------------------------------------------------------------
__global__ void __launch_bounds__(128) rec_kernel(const float* __restrict__ x,
                                                  const float* __restrict__ iw,
                                                  const float* __restrict__ lvec,
                                                  const float* __restrict__ bvec,
                                                  float* __restrict__ out) {
    __shared__ float xs[T_STEPS * N_IN];  // 12 KB
    const int b = blockIdx.x;
    const int h = blockIdx.y * 128 + threadIdx.x;

    for (int i = threadIdx.x; i < T_STEPS * N_IN; i += 128) {
        int t = i / N_IN, c = i - t * N_IN;
        xs[i] = x[((long)t * BATCH + b) * N_IN + c];
    }

    const float w0 = iw[0 * N_H + h];
    const float w1 = iw[1 * N_H + h];
    const float w2 = iw[2 * N_H + h];
    const float lv = lvec[h];
    const float bv = bvec[h];
    float y = g_h0[b * N_H + h];
    float s = g_c0[b * N_H + h];
    __syncthreads();

    float* yp1 = out + OFF_BOT + (long)b * N_H + h;
    float* yp2 = out + OFF_RNN + (long)b * N_H + h;
    float* sp  = out + OFF_CELL + (long)b * N_H + h;
    __half* yi = g_yimg + ((b * 512 + TSWZ(h * 2, b)) >> 1);

    const long strideT = (long)BATCH * N_H;  // 32768

    for (int t = 0; t < T_STEPS; t++) {
        const float x0 = xs[t * 3 + 0];
        const float x1 = xs[t * 3 + 1];
        const float x2 = xs[t * 3 + 2];
        float xw  = fmaf(x2, w2, fmaf(x1, w1, x0 * w0));
        float pre = xw + y + lv * s * (1.0f - y);
        s = fmaxf(pre, 0.0f);
        y = (s + bv > 0.0f) ? 1.0f : 0.0f;

        long o = (long)t * strideT;
        stcs1(yp1 + o, y);
        stcs1(yp2 + o, y);
        stcs1(sp + o, s);
        yi[(long)t * 32768] = __float2half_rn(y);
    }
}

// ---------------------------------------------------------------------------
// Kernel 4: pc GEMM via fp16 HMMA (single pass) + fused hd.
// grid=(1000,2), 256 thr, 136KB SMEM.
// ---------------------------------------------------------------------------
#define SM_A   0
#define SM_B   65536
#define SM_HD  131072
#define SM_TOT 139264

__global__ void __launch_bounds__(256) pc_gemm(const float* __restrict__ pcb,
                                               const float* __restrict__ hdb,
                                               float* __restrict__ out) {
    extern __shared__ char smem[];
    uint32_t sb = smem_u32(smem);
    const int tid = threadIdx.x, wid = tid >> 5, lane = tid & 31;
    const int m = blockIdx.x, nh = blockIdx.y;
    const int warp_m = wid & 3, warp_n = wid >> 2;
    const bool do_hd = (nh == 0) && (warp_n == 0);

    // Linear bulk copies of pre-swizzled images
    {
        const char* gA = (const char*)(g_yimg + (long)m * 32768);
        const char* gW = (const char*)(g_wimg[nh]);
        #pragma unroll
        for (int i = 0; i < 16; i++)
            cp_async16(sb + SM_A + (tid + i * 256) * 16, gA + (tid + i * 256) * 16);
        #pragma unroll
        for (int i = 0; i < 16; i++)
            cp_async16(sb + SM_B + (tid + i * 256) * 16, gW + (tid + i * 256) * 16);
        if (nh == 0) {
            const char* gH = (const char*)g_hdimg;
            #pragma unroll
            for (int i = 0; i < 2; i++)
                cp_async16(sb + SM_HD + (tid + i * 256) * 16, gH + (tid + i * 256) * 16);
        }
        cp_async_wait_all();
    }
    __syncthreads();

    float acc[2][8][4];
    #pragma unroll
    for (int i = 0; i < 2; i++)
        #pragma unroll
        for (int j = 0; j < 8; j++)
            #pragma unroll
            for (int q = 0; q < 4; q++) acc[i][j][q] = 0.0f;
    float acch[2][2][4];
    #pragma unroll
    for (int i = 0; i < 2; i++)
        #pragma unroll
        for (int j = 0; j < 2; j++)
            #pragma unroll
            for (int q = 0; q < 4; q++) acch[i][j][q] = 0.0f;

    const int arow0 = warp_m * 32 + (lane & 15);
    const int brow0 = warp_n * 64 + (lane & 15);
    const int hrow0 = (lane & 15);
    const int ksub  = (lane >> 4) * 16;

    #pragma unroll
    for (int k16 = 0; k16 < 16; k16++) {
        const int kb = k16 * 32 + ksub;
        uint32_t a[2][4], bfr[4][4];
        #pragma unroll
        for (int mi = 0; mi < 2; mi++) {
            int r = arow0 + mi * 16;
            ldsm4(a[mi][0], a[mi][1], a[mi][2], a[mi][3],
                  sb + SM_A + r * 512 + TSWZ(kb, r));
        }
        #pragma unroll
        for (int ni = 0; ni < 4; ni++) {
            int r = brow0 + ni * 16;
            ldsm4(bfr[ni][0], bfr[ni][1], bfr[ni][2], bfr[ni][3],
                  sb + SM_B + r * 512 + TSWZ(kb, r));
        }
        #pragma unroll
        for (int mi = 0; mi < 2; mi++)
            #pragma unroll
            for (int ni = 0; ni < 4; ni++) {
                mma16816(acc[mi][ni * 2],     a[mi], bfr[ni][0], bfr[ni][2]);
                mma16816(acc[mi][ni * 2 + 1], a[mi], bfr[ni][1], bfr[ni][3]);
            }
        if (do_hd) {
            uint32_t hb[4];
            ldsm4(hb[0], hb[1], hb[2], hb[3],
                  sb + SM_HD + hrow0 * 512 + TSWZ(kb, hrow0));
            #pragma unroll
            for (int mi = 0; mi < 2; mi++) {
                mma16816(acch[mi][0], a[mi], hb[0], hb[2]);
                mma16816(acch[mi][1], a[mi], hb[1], hb[3]);
            }
        }
    }

    // Epilogue: pc. c0,c1: row g; c2,c3: row g+8.
    const int g  = lane >> 2;
    const int c2 = (lane & 3) * 2;
    const long rowBase = (long)m * 128 + warp_m * 32;
    const int  colBase = nh * 128 + warp_n * 64;

    float2 bias2[8];
    #pragma unroll
    for (int ni = 0; ni < 8; ni++) {
        bias2[ni].x = __ldg(pcb + colBase + ni * 8 + c2);
        bias2[ni].y = __ldg(pcb + colBase + ni * 8 + c2 + 1);
    }

    float* outpc = out + OFF_PC;
    #pragma unroll
    for (int mi = 0; mi < 2; mi++) {
        float* r0 = outpc + (rowBase + mi * 16 + g) * N_PC + colBase + c2;
        float* r1 = r0 + 8 * N_PC;
        #pragma unroll
        for (int ni = 0; ni < 8; ni++) {
            stcs2(r0 + ni * 8, make_float2(acc[mi][ni][0] + bias2[ni].x,
                                           acc[mi][ni][1] + bias2[ni].y));
            stcs2(r1 + ni * 8, make_float2(acc[mi][ni][2] + bias2[ni].x,
                                           acc[mi][ni][3] + bias2[ni].y));
        }
    }

    // Epilogue: hd (cols 0..11 of the padded 16)
    if (do_hd) {
        float* outhd = out + OFF_HD;
        float hb0x = __ldg(hdb + c2);
        float hb0y = __ldg(hdb + c2 + 1);
        float hb1x = 0.0f, hb1y = 0.0f;
        if (c2 < 4) {
            hb1x = __ldg(hdb + 8 + c2);
            hb1y = __ldg(hdb + 8 + c2 + 1);
        }
        #pragma unroll
        for (int mi = 0; mi < 2; mi++) {
            long r = rowBase + mi * 16 + g;
            float* o0 = outhd + r * N_HD;
            float* o1 = o0 + 8L * N_HD;
            stcs2(o0 + c2, make_float2(acch[mi][0][0] + hb0x, acch[mi][0][1] + hb0y));
            stcs2(o1 + c2, make_float2(acch[mi][0][2] + hb0x, acch[mi][0][3] + hb0y));
            if (c2 < 4) {
                stcs2(o0 + 8 + c2, make_float2(acch[mi][1][0] + hb1x, acch[mi][1][1] + hb1y));
                stcs2(o1 + 8 + c2, make_float2(acch[mi][1][2] + hb1x, acch[mi][1][3] + hb1y));
            }
        }
    }
}

// ---------------------------------------------------------------------------
extern "C" void kernel_launch(void* const* d_in, const int* in_sizes, int n_in,
                              void* d_out, int out_size) {
    const float* x    = (const float*)d_in[0];
    const float* ic   = (const float*)d_in[1];
    const float* iw   = (const float*)d_in[2];
    const float* l    = (const float*)d_in[3];
    const float* b    = (const float*)d_in[4];
    const float* sew  = (const float*)d_in[5];
    const float* seb  = (const float*)d_in[6];
    const float* cew  = (const float*)d_in[7];
    const float* ceb  = (const float*)d_in[8];
    const float* pcw  = (const float*)d_in[9];
    const float* pcb  = (const float*)d_in[10];
    const float* hdw  = (const float*)d_in[11];
    const float* hdb  = (const float*)d_in[12];
    float* out = (float*)d_out;

    cudaFuncSetAttribute(pc_gemm, cudaFuncAttributeMaxDynamicSharedMemorySize, SM_TOT);

    init_kernel<<<BATCH, N_H>>>(ic, sew, seb, cew, ceb);
    wconv_kernel<<<256, 256>>>(pcw);
    wconv_hd_kernel<<<16, 256>>>(hdw);
    rec_kernel<<<dim3(BATCH, 2), 128>>>(x, iw, l, b, out);
    pc_gemm<<<dim3(T_STEPS, 2), 256, SM_TOT>>>(pcb, hdb, out);
}